// round 8
// baseline (speedup 1.0000x reference)
#include <cuda_runtime.h>
#include <cuda_bf16.h>
#include <cuda_fp16.h>
#include <cstdint>
#include <math.h>

#define BATCH 16
#define SEQ   2048
#define DE    256
#define DA    64
#define MTOT  (BATCH*SEQ)   // 32768

// ---------------- scratch ----------------
__device__ __half g_qh[MTOT * DA];     // 4 MB, [tok][d] fp16
__device__ __half g_kh[MTOT * DA];     // 4 MB, [tok][d] fp16
__device__ __half g_vh[MTOT * DE];     // 16 MB, key-interleaved [tok/2][d][tok&1]
__device__ float  g_attn[MTOT * DE];   // 32 MB
__device__ float  g_h[MTOT * DE];      // 32 MB
__device__ float  g_sum[DE];
__device__ float  g_sumsq[DE];

// ================= helpers =================
__device__ __forceinline__ uint32_t smem_to_u32(const void* p) {
    uint32_t a;
    asm("{ .reg .u64 t; cvta.to.shared.u64 t, %1; cvt.u32.u64 %0, t; }" : "=r"(a) : "l"(p));
    return a;
}
__device__ __forceinline__ void mma_tf32(float* c, const uint32_t* a,
                                         uint32_t b0, uint32_t b1) {
    asm volatile(
        "mma.sync.aligned.m16n8k8.row.col.f32.tf32.tf32.f32 "
        "{%0,%1,%2,%3}, {%4,%5,%6,%7}, {%8,%9}, {%0,%1,%2,%3};"
        : "+f"(c[0]), "+f"(c[1]), "+f"(c[2]), "+f"(c[3])
        : "r"(a[0]), "r"(a[1]), "r"(a[2]), "r"(a[3]), "r"(b0), "r"(b1));
}
__device__ __forceinline__ void mma_f16(float* c, const uint32_t* a,
                                        uint32_t b0, uint32_t b1) {
    asm volatile(
        "mma.sync.aligned.m16n8k16.row.col.f32.f16.f16.f32 "
        "{%0,%1,%2,%3}, {%4,%5,%6,%7}, {%8,%9}, {%0,%1,%2,%3};"
        : "+f"(c[0]), "+f"(c[1]), "+f"(c[2]), "+f"(c[3])
        : "r"(a[0]), "r"(a[1]), "r"(a[2]), "r"(a[3]), "r"(b0), "r"(b1));
}
__device__ __forceinline__ void cp_async16(uint32_t dst, const void* src) {
    asm volatile("cp.async.cg.shared.global [%0], [%1], 16;" :: "r"(dst), "l"(src));
}

// ---------------- mma.sync tf32 GEMM with fp16 output modes ----------------
// mode 0: fp32 [row][col]   mode 1: fp16 [row][col]   mode 2: fp16 interleaved V
#define GA_F 4096
#define GW_F 2048
#define GEMM_SMEM ((2*GA_F + 2*GW_F)*4)

__global__ void __launch_bounds__(256)
gemm_mma_kernel(const float* __restrict__ A,
                const float* __restrict__ W,
                const float* __restrict__ bias,
                void* __restrict__ Cout, int Ncols, int mode) {
    extern __shared__ float sm[];
    float* smA = sm;
    float* smW = sm + 2 * GA_F;
    const uint32_t sbA = smem_to_u32(smA);
    const uint32_t sbW = smem_to_u32(smW);

    const int tid = threadIdx.x;
    const int lane = tid & 31, w = tid >> 5;
    const int g = lane >> 2, t = lane & 3;
    const int mw = w >> 1, nw = w & 1;
    const int bm = blockIdx.x * 128;
    const int bn = blockIdx.y * 64;

    float c[2][4][4];
    #pragma unroll
    for (int mb = 0; mb < 2; mb++)
        #pragma unroll
        for (int nb = 0; nb < 4; nb++)
            c[mb][nb][0] = c[mb][nb][1] = c[mb][nb][2] = c[mb][nb][3] = 0.f;

    auto issue2 = [&](int chunk, int stage) {
        const int k0 = chunk * 32;
        #pragma unroll
        for (int i = 0; i < 4; i++) {
            int idx = tid + i * 256;
            int m = idx >> 3, k4 = idx & 7;
            cp_async16(sbA + (uint32_t)(stage * GA_F + m * 32 + (k4 ^ (m & 7)) * 4) * 4u,
                       A + (size_t)(bm + m) * 256 + k0 + k4 * 4);
        }
        #pragma unroll
        for (int i = 0; i < 2; i++) {
            int idx = tid + i * 256;
            int kk = idx >> 4, n4 = idx & 15;
            cp_async16(sbW + (uint32_t)(stage * GW_F + kk * 64 + (n4 ^ (2 * (kk & 3))) * 4) * 4u,
                       W + (size_t)(k0 + kk) * Ncols + bn + n4 * 4);
        }
    };

    issue2(0, 0);
    asm volatile("cp.async.commit_group;" ::: "memory");

    for (int ch = 0; ch < 8; ch++) {
        if (ch + 1 < 8) {
            issue2(ch + 1, (ch + 1) & 1);
            asm volatile("cp.async.commit_group;" ::: "memory");
            asm volatile("cp.async.wait_group 1;" ::: "memory");
        } else {
            asm volatile("cp.async.wait_group 0;" ::: "memory");
        }
        __syncthreads();

        const float* cA = smA + (ch & 1) * GA_F;
        const float* cW = smW + (ch & 1) * GW_F;

        uint32_t af[4][2][4];
        #pragma unroll
        for (int ks = 0; ks < 4; ks++) {
            #pragma unroll
            for (int mb = 0; mb < 2; mb++) {
                int r0 = mw * 32 + mb * 16 + g;
                int r8 = r0 + 8;
                int kA = ks * 8 + t;
                af[ks][mb][0] = __float_as_uint(cA[r0 * 32 + (((kA) >> 2) ^ (r0 & 7)) * 4 + (kA & 3)]);
                af[ks][mb][1] = __float_as_uint(cA[r8 * 32 + (((kA) >> 2) ^ (r8 & 7)) * 4 + (kA & 3)]);
                int kB = kA + 4;
                af[ks][mb][2] = __float_as_uint(cA[r0 * 32 + (((kB) >> 2) ^ (r0 & 7)) * 4 + (kB & 3)]);
                af[ks][mb][3] = __float_as_uint(cA[r8 * 32 + (((kB) >> 2) ^ (r8 & 7)) * 4 + (kB & 3)]);
            }
        }
        uint32_t bf[4][4][2];
        #pragma unroll
        for (int ks = 0; ks < 4; ks++) {
            #pragma unroll
            for (int nb = 0; nb < 4; nb++) {
                int n = nw * 32 + nb * 8 + g;
                int k1 = ks * 8 + t;
                int k2 = k1 + 4;
                bf[ks][nb][0] = __float_as_uint(cW[k1 * 64 + ((n >> 2) ^ (2 * (k1 & 3))) * 4 + (n & 3)]);
                bf[ks][nb][1] = __float_as_uint(cW[k2 * 64 + ((n >> 2) ^ (2 * (k2 & 3))) * 4 + (n & 3)]);
            }
        }
        #pragma unroll
        for (int ks = 0; ks < 4; ks++)
            #pragma unroll
            for (int mb = 0; mb < 2; mb++)
                #pragma unroll
                for (int nb = 0; nb < 4; nb++)
                    mma_tf32(c[mb][nb], af[ks][mb], bf[ks][nb][0], bf[ks][nb][1]);
        __syncthreads();
    }

    #pragma unroll
    for (int nb = 0; nb < 4; nb++) {
        int col = bn + nw * 32 + nb * 8 + 2 * t;
        float b0 = bias[col], b1 = bias[col + 1];
        #pragma unroll
        for (int mb = 0; mb < 2; mb++) {
            int row = bm + mw * 32 + mb * 16 + g;
            float v00 = c[mb][nb][0] + b0, v01 = c[mb][nb][1] + b1;
            float v10 = c[mb][nb][2] + b0, v11 = c[mb][nb][3] + b1;
            if (mode == 0) {
                float* C = (float*)Cout;
                *(float2*)&C[(size_t)row * Ncols + col] = make_float2(v00, v01);
                *(float2*)&C[(size_t)(row + 8) * Ncols + col] = make_float2(v10, v11);
            } else if (mode == 1) {
                __half2* C2 = (__half2*)Cout;
                C2[((size_t)row * Ncols + col) >> 1] = __floats2half2_rn(v00, v01);
                C2[((size_t)(row + 8) * Ncols + col) >> 1] = __floats2half2_rn(v10, v11);
            } else {
                __half* Ch = (__half*)Cout;
                int r2 = row + 8;
                Ch[(size_t)(row >> 1) * 512 + col * 2 + (row & 1)]       = __float2half_rn(v00);
                Ch[(size_t)(row >> 1) * 512 + (col + 1) * 2 + (row & 1)] = __float2half_rn(v01);
                Ch[(size_t)(r2 >> 1) * 512 + col * 2 + (r2 & 1)]         = __float2half_rn(v10);
                Ch[(size_t)(r2 >> 1) * 512 + (col + 1) * 2 + (r2 & 1)]   = __float2half_rn(v11);
            }
        }
    }
}

// ---------------- fp16 mma.sync flash attention, 512 threads ----------------
// CTA = 128 queries, 16 warps, 64-key tiles, double-buffered K/V fp16.
// S phase:  warp = (q-group w>>1 of 16q) x (key-half w&1 of 32 keys): M=16,N=32.
// PV phase: warp = (q-quarter w>>2 of 32q) x (d-group w&3 of 64d):    M=32,N=64.
#define KSTRH 72
#define KFH   (64*KSTRH)            // 4608 halfs
#define VSTRW 264
#define VFW   (32*VSTRW)            // 8448 words
#define STGH  (KFH + 2*VFW)         // 21504 halfs per stage
#define PSTRH 72
#define PFH   (128*PSTRH)           // 9216 halfs
#define ATTN_SMEM (2*STGH*2 + PFH*2 + 256*4)   // 105472 bytes

__global__ void __launch_bounds__(512, 1)
attn_mma_kernel(const __half* __restrict__ q,
                const __half* __restrict__ k,
                const __half* __restrict__ v,
                float* __restrict__ out) {
    extern __shared__ __half smh[];
    __half* smP = smh + 2 * STGH;
    float* smL = (float*)(smh + 2 * STGH + PFH);
    const uint32_t sbase = smem_to_u32(smh);
    const int tid = threadIdx.x;
    const int lane = tid & 31, w = tid >> 5;
    const int g = lane >> 2, t = lane & 3;
    const int b = blockIdx.y;
    const int q0 = blockIdx.x * 128;

    const int qg = w >> 1, kh = w & 1;   // S-phase mapping (16 q-groups? no: 8)
    const int qq = w >> 2, dg = w & 3;   // PV-phase mapping

    const __half* kb = k + (size_t)b * SEQ * DA;
    const __half* vb = v + (size_t)b * SEQ * DE;   // interleaved within batch

    // Q A-fragments (m16n8k16): warp owns 16 queries (qg in [0,8))
    uint32_t qa[4][4];
    {
        const __half* r0 = q + (size_t)(b * SEQ + q0 + qg * 16 + g) * DA;
        const __half* r8 = r0 + 8 * DA;
        #pragma unroll
        for (int ks = 0; ks < 4; ks++) {
            qa[ks][0] = *(const uint32_t*)(r0 + ks * 16 + 2 * t);
            qa[ks][1] = *(const uint32_t*)(r8 + ks * 16 + 2 * t);
            qa[ks][2] = *(const uint32_t*)(r0 + ks * 16 + 2 * t + 8);
            qa[ks][3] = *(const uint32_t*)(r8 + ks * 16 + 2 * t + 8);
        }
    }

    float o[2][8][4];
    #pragma unroll
    for (int m = 0; m < 2; m++)
        #pragma unroll
        for (int nb = 0; nb < 8; nb++)
            o[m][nb][0] = o[m][nb][1] = o[m][nb][2] = o[m][nb][3] = 0.f;
    float rs[2] = {0.f, 0.f};

    auto issue = [&](int tile, int stage) {
        const uint32_t kd = sbase + (uint32_t)(stage * STGH) * 2u;
        const uint32_t vd = kd + (uint32_t)KFH * 2u;
        const __half* ksrc = kb + (size_t)tile * 64 * DA;
        const __half* vsrc = vb + (size_t)tile * 32 * 512;
        {   // K: 512 x 16B, 1 per thread
            int r = tid >> 3, c16 = tid & 7;
            cp_async16(kd + (uint32_t)(r * KSTRH * 2 + c16 * 16), ksrc + r * 64 + c16 * 8);
        }
        #pragma unroll
        for (int i = 0; i < 4; i++) {            // V: 2048 x 16B
            int idx = tid + i * 512;
            int r = idx >> 6, ch = idx & 63;
            cp_async16(vd + (uint32_t)(r * VSTRW * 4 + ch * 16), vsrc + (size_t)r * 512 + ch * 8);
        }
    };

    issue(0, 0);
    asm volatile("cp.async.commit_group;" ::: "memory");

    for (int tile = 0; tile < SEQ / 64; tile++) {
        if (tile + 1 < SEQ / 64) {
            issue(tile + 1, (tile + 1) & 1);
            asm volatile("cp.async.commit_group;" ::: "memory");
            asm volatile("cp.async.wait_group 1;" ::: "memory");
        } else {
            asm volatile("cp.async.wait_group 0;" ::: "memory");
        }
        __syncthreads();

        const __half* sK = smh + (tile & 1) * STGH;
        const uint32_t* sVw = (const uint32_t*)(sK + KFH);

        // ---- S: 16 q x 32 keys per warp ----
        float c[4][4];
        #pragma unroll
        for (int nb = 0; nb < 4; nb++)
            c[nb][0] = c[nb][1] = c[nb][2] = c[nb][3] = 0.f;
        #pragma unroll
        for (int ks = 0; ks < 4; ks++) {
            #pragma unroll
            for (int nb = 0; nb < 4; nb++) {
                const __half* kr = sK + (kh * 32 + nb * 8 + g) * KSTRH + ks * 16 + 2 * t;
                uint32_t b0 = *(const uint32_t*)kr;
                uint32_t b1 = *(const uint32_t*)(kr + 8);
                mma_f16(c[nb], qa[ks], b0, b1);
            }
        }

        // ---- P = exp(S/64) -> smem fp16, accumulate row sums ----
        {
            __half* pr = smP + (qg * 16 + g) * PSTRH + kh * 32;
            __half* pr8 = pr + 8 * PSTRH;
            #pragma unroll
            for (int nb = 0; nb < 4; nb++) {
                float e0 = __expf(c[nb][0] * 0.015625f);
                float e1 = __expf(c[nb][1] * 0.015625f);
                float e2 = __expf(c[nb][2] * 0.015625f);
                float e3 = __expf(c[nb][3] * 0.015625f);
                rs[0] += e0 + e1;
                rs[1] += e2 + e3;
                *(__half2*)(pr + nb * 8 + 2 * t) = __floats2half2_rn(e0, e1);
                *(__half2*)(pr8 + nb * 8 + 2 * t) = __floats2half2_rn(e2, e3);
            }
        }
        __syncthreads();

        // ---- O += P @ V : 32 q x 64 d per warp ----
        #pragma unroll
        for (int ks = 0; ks < 4; ks++) {
            uint32_t pf[2][4];
            #pragma unroll
            for (int m = 0; m < 2; m++) {
                const __half* p0 = smP + (qq * 32 + m * 16 + g) * PSTRH + ks * 16 + 2 * t;
                pf[m][0] = *(const uint32_t*)p0;
                pf[m][1] = *(const uint32_t*)(p0 + 8 * PSTRH);
                pf[m][2] = *(const uint32_t*)(p0 + 8);
                pf[m][3] = *(const uint32_t*)(p0 + 8 * PSTRH + 8);
            }
            #pragma unroll
            for (int nb = 0; nb < 8; nb++) {
                const uint32_t* vw = sVw + (ks * 8 + t) * VSTRW + dg * 64 + nb * 8 + g;
                uint32_t b0 = vw[0];
                uint32_t b1 = vw[4 * VSTRW];
                #pragma unroll
                for (int m = 0; m < 2; m++)
                    mma_f16(o[m][nb], pf[m], b0, b1);
            }
        }
        __syncthreads();
    }

    // ---- row-sum reduction across quad lanes + 2 key-half warps ----
    #pragma unroll
    for (int r = 0; r < 2; r++) {
        rs[r] += __shfl_xor_sync(0xffffffff, rs[r], 1);
        rs[r] += __shfl_xor_sync(0xffffffff, rs[r], 2);
    }
    if (t == 0) {
        #pragma unroll
        for (int r = 0; r < 2; r++)
            smL[kh * 128 + qg * 16 + r * 8 + g] = rs[r];
    }
    __syncthreads();

    // ---- epilogue ----
    #pragma unroll
    for (int m = 0; m < 2; m++) {
        int qrow = qq * 32 + m * 16 + g;
        float inv0 = 1.f / (smL[qrow] + smL[128 + qrow]);
        float inv8 = 1.f / (smL[qrow + 8] + smL[128 + qrow + 8]);
        float* out0 = out + (size_t)(b * SEQ + q0 + qrow) * DE + dg * 64;
        float* out8 = out0 + 8 * DE;
        #pragma unroll
        for (int nb = 0; nb < 8; nb++) {
            *(float2*)&out0[nb * 8 + 2 * t] =
                make_float2(o[m][nb][0] * inv0, o[m][nb][1] * inv0);
            *(float2*)&out8[nb * 8 + 2 * t] =
                make_float2(o[m][nb][2] * inv8, o[m][nb][3] * inv8);
        }
    }
}

// ---------------- BatchNorm pieces ----------------
__global__ void bn_zero_kernel() {
    int tidx = threadIdx.x;
    g_sum[tidx] = 0.f;
    g_sumsq[tidx] = 0.f;
}

__global__ void bn_stats_kernel(const float* __restrict__ h) {
    const int c = threadIdx.x;
    const int r0 = blockIdx.x * 128;
    float s = 0.f, s2 = 0.f;
    #pragma unroll 4
    for (int r = 0; r < 128; r++) {
        float x = h[(size_t)(r0 + r) * DE + c];
        s += x;
        s2 += x * x;
    }
    atomicAdd(&g_sum[c], s);
    atomicAdd(&g_sumsq[c], s2);
}

__global__ void bn_finalize_kernel(const float* __restrict__ h,
                                   const float* __restrict__ x,
                                   const float* __restrict__ gamma,
                                   const float* __restrict__ beta,
                                   float* __restrict__ y) {
    const int idx = blockIdx.x * 256 + threadIdx.x;
    const int c0 = (idx * 4) & 255;
    const float invM = 1.f / (float)MTOT;
    float4 hv = ((const float4*)h)[idx];
    float4 xv = ((const float4*)x)[idx];
    float r[4];
    float hvv[4] = {hv.x, hv.y, hv.z, hv.w};
    float xvv[4] = {xv.x, xv.y, xv.z, xv.w};
    #pragma unroll
    for (int u = 0; u < 4; u++) {
        int c = c0 + u;
        float mean = g_sum[c] * invM;
        float var = g_sumsq[c] * invM - mean * mean;
        float rsv = rsqrtf(var + 1e-5f);
        float val = (hvv[u] - mean) * rsv * gamma[c] + beta[c];
        r[u] = fmaxf(val, 0.f) + xvv[u];
    }
    float4 ov = {r[0], r[1], r[2], r[3]};
    ((float4*)y)[idx] = ov;
}

// ---------------- launch ----------------
extern "C" void kernel_launch(void* const* d_in, const int* in_sizes, int n_in,
                              void* d_out, int out_size) {
    const float* x     = (const float*)d_in[0];
    const float* Wq    = (const float*)d_in[1];
    const float* bq    = (const float*)d_in[2];
    const float* Wk    = (const float*)d_in[3];
    const float* bk    = (const float*)d_in[4];
    const float* Wv    = (const float*)d_in[5];
    const float* bv    = (const float*)d_in[6];
    const float* Wl    = (const float*)d_in[7];
    const float* bl    = (const float*)d_in[8];
    const float* gamma = (const float*)d_in[9];
    const float* beta  = (const float*)d_in[10];
    float* out = (float*)d_out;

    __half *pqh, *pkh, *pvh;
    float *pattn, *ph;
    cudaGetSymbolAddress((void**)&pqh, g_qh);
    cudaGetSymbolAddress((void**)&pkh, g_kh);
    cudaGetSymbolAddress((void**)&pvh, g_vh);
    cudaGetSymbolAddress((void**)&pattn, g_attn);
    cudaGetSymbolAddress((void**)&ph, g_h);

    cudaFuncSetAttribute(attn_mma_kernel, cudaFuncAttributeMaxDynamicSharedMemorySize,
                         ATTN_SMEM);
    cudaFuncSetAttribute(gemm_mma_kernel, cudaFuncAttributeMaxDynamicSharedMemorySize,
                         GEMM_SMEM);

    // projections (tf32 compute, fp16 outputs)
    gemm_mma_kernel<<<dim3(MTOT / 128, 1), 256, GEMM_SMEM>>>(x, Wq, bq, pqh, DA, 1);
    gemm_mma_kernel<<<dim3(MTOT / 128, 1), 256, GEMM_SMEM>>>(x, Wk, bk, pkh, DA, 1);
    gemm_mma_kernel<<<dim3(MTOT / 128, 4), 256, GEMM_SMEM>>>(x, Wv, bv, pvh, DE, 2);

    // attention (fp16 m16n8k16, 512 threads)
    attn_mma_kernel<<<dim3(SEQ / 128, BATCH), 512, ATTN_SMEM>>>(pqh, pkh, pvh, pattn);

    // h = attn @ Wl + bl (tf32, fp32 out)
    gemm_mma_kernel<<<dim3(MTOT / 128, 4), 256, GEMM_SMEM>>>(pattn, Wl, bl, ph, DE, 0);

    // batchnorm + relu + residual
    bn_zero_kernel<<<1, 256>>>();
    bn_stats_kernel<<<MTOT / 128, 256>>>(ph);
    bn_finalize_kernel<<<(MTOT * DE) / 4 / 256, 256>>>(ph, x, gamma, beta, out);
}

// round 9
// speedup vs baseline: 1.0916x; 1.0916x over previous
#include <cuda_runtime.h>
#include <cuda_bf16.h>
#include <cuda_fp16.h>
#include <cstdint>
#include <math.h>

#define BATCH 16
#define SEQ   2048
#define DE    256
#define DA    64
#define MTOT  (BATCH*SEQ)   // 32768

// ---------------- scratch ----------------
__device__ __half g_xh[MTOT * DE];     // 16 MB, x fp16 [tok][d]
__device__ __half g_qh[MTOT * DA];     // 4 MB
__device__ __half g_kh[MTOT * DA];     // 4 MB
__device__ __half g_vh[MTOT * DE];     // 16 MB, key-interleaved [tok/2][d][tok&1]
__device__ __half g_attnh[MTOT * DE];  // 16 MB, attn fp16 [tok][d]
__device__ float  g_h[MTOT * DE];      // 32 MB
__device__ __half g_wqt[DA * DE];      // transposed fp16 weights [n][k]
__device__ __half g_wkt[DA * DE];
__device__ __half g_wvt[DE * DE];
__device__ __half g_wlt[DE * DE];
__device__ float  g_sum[DE];
__device__ float  g_sumsq[DE];

// ================= helpers =================
__device__ __forceinline__ uint32_t smem_to_u32(const void* p) {
    uint32_t a;
    asm("{ .reg .u64 t; cvta.to.shared.u64 t, %1; cvt.u32.u64 %0, t; }" : "=r"(a) : "l"(p));
    return a;
}
__device__ __forceinline__ void mma_f16(float* c, const uint32_t* a,
                                        uint32_t b0, uint32_t b1) {
    asm volatile(
        "mma.sync.aligned.m16n8k16.row.col.f32.f16.f16.f32 "
        "{%0,%1,%2,%3}, {%4,%5,%6,%7}, {%8,%9}, {%0,%1,%2,%3};"
        : "+f"(c[0]), "+f"(c[1]), "+f"(c[2]), "+f"(c[3])
        : "r"(a[0]), "r"(a[1]), "r"(a[2]), "r"(a[3]), "r"(b0), "r"(b1));
}
__device__ __forceinline__ void cp_async16(uint32_t dst, const void* src) {
    asm volatile("cp.async.cg.shared.global [%0], [%1], 16;" :: "r"(dst), "l"(src));
}

// ---------------- conversion kernels ----------------
__global__ void conv_x_kernel(const float* __restrict__ x, __half* __restrict__ xh) {
    const int idx = blockIdx.x * 256 + threadIdx.x;     // float4 index
    float4 f = ((const float4*)x)[idx];
    __half2 h0 = __floats2half2_rn(f.x, f.y);
    __half2 h1 = __floats2half2_rn(f.z, f.w);
    ((__half2*)xh)[idx * 2] = h0;
    ((__half2*)xh)[idx * 2 + 1] = h1;
}

// W [256, N] fp32 -> Wt [N][256] fp16
__global__ void conv_wt_kernel(const float* __restrict__ W, __half* __restrict__ Wt, int N) {
    const int idx = blockIdx.x * 256 + threadIdx.x;     // over N*256
    if (idx < N * 256) {
        int n = idx >> 8, kk = idx & 255;
        Wt[idx] = __float2half_rn(W[kk * N + n]);
    }
}

// ---------------- fp16 mma.sync GEMM ----------------
// C[M,Nc] = A[M,256] @ Wt^T + bias.  A fp16 [M][256], Wt fp16 [Nc][256].
// BM=128, BN=64, BK=64 halfs, 256 threads (8 warps), warp tile 32m x 32n.
// modes: 0 fp32 [row][col], 1 fp16 [row][col], 2 fp16 V-interleaved.
#define HA_H (128*72)
#define HW_H (64*72)
#define GEMMH_SMEM ((2*HA_H + 2*HW_H)*2)   // 55296 bytes

__global__ void __launch_bounds__(256)
gemm_f16_kernel(const __half* __restrict__ A,
                const __half* __restrict__ Wt,
                const float* __restrict__ bias,
                void* __restrict__ Cout, int Ncols, int mode) {
    extern __shared__ __half smg[];
    __half* smA = smg;
    __half* smW = smg + 2 * HA_H;
    const uint32_t sbA = smem_to_u32(smA);
    const uint32_t sbW = smem_to_u32(smW);

    const int tid = threadIdx.x;
    const int lane = tid & 31, w = tid >> 5;
    const int g = lane >> 2, t = lane & 3;
    const int mw = w >> 1, nw = w & 1;
    const int bm = blockIdx.x * 128;
    const int bn = blockIdx.y * 64;

    float c[2][4][4];
    #pragma unroll
    for (int mb = 0; mb < 2; mb++)
        #pragma unroll
        for (int nb = 0; nb < 4; nb++)
            c[mb][nb][0] = c[mb][nb][1] = c[mb][nb][2] = c[mb][nb][3] = 0.f;

    auto issue = [&](int chunk, int stage) {
        const int k0 = chunk * 64;
        #pragma unroll
        for (int i = 0; i < 4; i++) {            // A: 1024 x 16B
            int idx = tid + i * 256;
            int r = idx >> 3, c16 = idx & 7;
            cp_async16(sbA + (uint32_t)(stage * HA_H + r * 72 + c16 * 8) * 2u,
                       A + (size_t)(bm + r) * 256 + k0 + c16 * 8);
        }
        #pragma unroll
        for (int i = 0; i < 2; i++) {            // Wt: 512 x 16B
            int idx = tid + i * 256;
            int r = idx >> 3, c16 = idx & 7;
            cp_async16(sbW + (uint32_t)(stage * HW_H + r * 72 + c16 * 8) * 2u,
                       Wt + (size_t)(bn + r) * 256 + k0 + c16 * 8);
        }
    };

    issue(0, 0);
    asm volatile("cp.async.commit_group;" ::: "memory");

    for (int ch = 0; ch < 4; ch++) {
        if (ch + 1 < 4) {
            issue(ch + 1, (ch + 1) & 1);
            asm volatile("cp.async.commit_group;" ::: "memory");
            asm volatile("cp.async.wait_group 1;" ::: "memory");
        } else {
            asm volatile("cp.async.wait_group 0;" ::: "memory");
        }
        __syncthreads();

        const __half* cA = smA + (ch & 1) * HA_H;
        const __half* cW = smW + (ch & 1) * HW_H;

        #pragma unroll
        for (int ks = 0; ks < 4; ks++) {
            uint32_t af[2][4];
            #pragma unroll
            for (int mb = 0; mb < 2; mb++) {
                const __half* p = cA + (mw * 32 + mb * 16 + g) * 72 + ks * 16 + 2 * t;
                af[mb][0] = *(const uint32_t*)p;
                af[mb][1] = *(const uint32_t*)(p + 8 * 72);
                af[mb][2] = *(const uint32_t*)(p + 8);
                af[mb][3] = *(const uint32_t*)(p + 8 * 72 + 8);
            }
            #pragma unroll
            for (int nb = 0; nb < 4; nb++) {
                const __half* p = cW + (nw * 32 + nb * 8 + g) * 72 + ks * 16 + 2 * t;
                uint32_t b0 = *(const uint32_t*)p;
                uint32_t b1 = *(const uint32_t*)(p + 8);
                #pragma unroll
                for (int mb = 0; mb < 2; mb++)
                    mma_f16(c[mb][nb], af[mb], b0, b1);
            }
        }
        __syncthreads();
    }

    #pragma unroll
    for (int nb = 0; nb < 4; nb++) {
        int col = bn + nw * 32 + nb * 8 + 2 * t;
        float b0 = bias[col], b1 = bias[col + 1];
        #pragma unroll
        for (int mb = 0; mb < 2; mb++) {
            int row = bm + mw * 32 + mb * 16 + g;
            float v00 = c[mb][nb][0] + b0, v01 = c[mb][nb][1] + b1;
            float v10 = c[mb][nb][2] + b0, v11 = c[mb][nb][3] + b1;
            if (mode == 0) {
                float* C = (float*)Cout;
                *(float2*)&C[(size_t)row * Ncols + col] = make_float2(v00, v01);
                *(float2*)&C[(size_t)(row + 8) * Ncols + col] = make_float2(v10, v11);
            } else if (mode == 1) {
                __half2* C2 = (__half2*)Cout;
                C2[((size_t)row * Ncols + col) >> 1] = __floats2half2_rn(v00, v01);
                C2[((size_t)(row + 8) * Ncols + col) >> 1] = __floats2half2_rn(v10, v11);
            } else {
                __half* Ch = (__half*)Cout;
                int r2 = row + 8;
                Ch[(size_t)(row >> 1) * 512 + col * 2 + (row & 1)]       = __float2half_rn(v00);
                Ch[(size_t)(row >> 1) * 512 + (col + 1) * 2 + (row & 1)] = __float2half_rn(v01);
                Ch[(size_t)(r2 >> 1) * 512 + col * 2 + (r2 & 1)]         = __float2half_rn(v10);
                Ch[(size_t)(r2 >> 1) * 512 + (col + 1) * 2 + (r2 & 1)]   = __float2half_rn(v11);
            }
        }
    }
}

// ---------------- fp16 mma.sync flash attention (R7 config, fp16 output) ----
// CTA = 128 queries, 8 warps (256 thr), 64-key tiles, double-buffered K/V fp16.
#define KSTRH 72
#define KFH   (64*KSTRH)
#define VSTRW 264
#define VFW   (32*VSTRW)
#define STGH  (KFH + 2*VFW)
#define PSTRH 72
#define PFH   (128*PSTRH)
#define ATTN_SMEM (2*STGH*2 + PFH*2 + 256*4)   // 105472 bytes

__global__ void __launch_bounds__(256, 1)
attn_mma_kernel(const __half* __restrict__ q,
                const __half* __restrict__ k,
                const __half* __restrict__ v,
                __half* __restrict__ out) {
    extern __shared__ __half smh[];
    __half* smP = smh + 2 * STGH;
    float* smL = (float*)(smh + 2 * STGH + PFH);
    const uint32_t sbase = smem_to_u32(smh);
    const int tid = threadIdx.x;
    const int lane = tid & 31, w = tid >> 5;
    const int g = lane >> 2, t = lane & 3;
    const int b = blockIdx.y;
    const int q0 = blockIdx.x * 128;

    const int qg = w >> 1, kh = w & 1;   // S-phase mapping
    const int qh = w >> 2, dg = w & 3;   // PV-phase mapping

    const __half* kb = k + (size_t)b * SEQ * DA;
    const __half* vb = v + (size_t)b * SEQ * DE;

    uint32_t qa[2][4][4];
    {
        const __half* qbase = q + (size_t)(b * SEQ + q0 + qg * 32) * DA;
        #pragma unroll
        for (int m = 0; m < 2; m++) {
            const __half* r0 = qbase + (size_t)(m * 16 + g) * DA;
            const __half* r8 = r0 + 8 * DA;
            #pragma unroll
            for (int ks = 0; ks < 4; ks++) {
                qa[m][ks][0] = *(const uint32_t*)(r0 + ks * 16 + 2 * t);
                qa[m][ks][1] = *(const uint32_t*)(r8 + ks * 16 + 2 * t);
                qa[m][ks][2] = *(const uint32_t*)(r0 + ks * 16 + 2 * t + 8);
                qa[m][ks][3] = *(const uint32_t*)(r8 + ks * 16 + 2 * t + 8);
            }
        }
    }

    float o[4][8][4];
    #pragma unroll
    for (int m = 0; m < 4; m++)
        #pragma unroll
        for (int nb = 0; nb < 8; nb++)
            o[m][nb][0] = o[m][nb][1] = o[m][nb][2] = o[m][nb][3] = 0.f;
    float rs[2][2] = {{0.f, 0.f}, {0.f, 0.f}};

    auto issue = [&](int tile, int stage) {
        const uint32_t kd = sbase + (uint32_t)(stage * STGH) * 2u;
        const uint32_t vd = kd + (uint32_t)KFH * 2u;
        const __half* ksrc = kb + (size_t)tile * 64 * DA;
        const __half* vsrc = vb + (size_t)tile * 32 * 512;
        #pragma unroll
        for (int i = 0; i < 2; i++) {
            int idx = tid + i * 256;
            int r = idx >> 3, c16 = idx & 7;
            cp_async16(kd + (uint32_t)(r * KSTRH * 2 + c16 * 16), ksrc + r * 64 + c16 * 8);
        }
        #pragma unroll
        for (int i = 0; i < 8; i++) {
            int idx = tid + i * 256;
            int r = idx >> 6, ch = idx & 63;
            cp_async16(vd + (uint32_t)(r * VSTRW * 4 + ch * 16), vsrc + (size_t)r * 512 + ch * 8);
        }
    };

    issue(0, 0);
    asm volatile("cp.async.commit_group;" ::: "memory");

    for (int tile = 0; tile < SEQ / 64; tile++) {
        if (tile + 1 < SEQ / 64) {
            issue(tile + 1, (tile + 1) & 1);
            asm volatile("cp.async.commit_group;" ::: "memory");
            asm volatile("cp.async.wait_group 1;" ::: "memory");
        } else {
            asm volatile("cp.async.wait_group 0;" ::: "memory");
        }
        __syncthreads();

        const __half* sK = smh + (tile & 1) * STGH;
        const uint32_t* sVw = (const uint32_t*)(sK + KFH);

        float c[2][4][4];
        #pragma unroll
        for (int m = 0; m < 2; m++)
            #pragma unroll
            for (int nb = 0; nb < 4; nb++)
                c[m][nb][0] = c[m][nb][1] = c[m][nb][2] = c[m][nb][3] = 0.f;
        #pragma unroll
        for (int ks = 0; ks < 4; ks++) {
            #pragma unroll
            for (int nb = 0; nb < 4; nb++) {
                const __half* kr = sK + (kh * 32 + nb * 8 + g) * KSTRH + ks * 16 + 2 * t;
                uint32_t b0 = *(const uint32_t*)kr;
                uint32_t b1 = *(const uint32_t*)(kr + 8);
                mma_f16(c[0][nb], qa[0][ks], b0, b1);
                mma_f16(c[1][nb], qa[1][ks], b0, b1);
            }
        }

        #pragma unroll
        for (int m = 0; m < 2; m++) {
            __half* pr = smP + (qg * 32 + m * 16 + g) * PSTRH + kh * 32;
            __half* pr8 = pr + 8 * PSTRH;
            #pragma unroll
            for (int nb = 0; nb < 4; nb++) {
                float e0 = __expf(c[m][nb][0] * 0.015625f);
                float e1 = __expf(c[m][nb][1] * 0.015625f);
                float e2 = __expf(c[m][nb][2] * 0.015625f);
                float e3 = __expf(c[m][nb][3] * 0.015625f);
                rs[m][0] += e0 + e1;
                rs[m][1] += e2 + e3;
                *(__half2*)(pr + nb * 8 + 2 * t) = __floats2half2_rn(e0, e1);
                *(__half2*)(pr8 + nb * 8 + 2 * t) = __floats2half2_rn(e2, e3);
            }
        }
        __syncthreads();

        #pragma unroll
        for (int ks = 0; ks < 4; ks++) {
            uint32_t pf[4][4];
            #pragma unroll
            for (int m = 0; m < 4; m++) {
                const __half* p0 = smP + (qh * 64 + m * 16 + g) * PSTRH + ks * 16 + 2 * t;
                pf[m][0] = *(const uint32_t*)p0;
                pf[m][1] = *(const uint32_t*)(p0 + 8 * PSTRH);
                pf[m][2] = *(const uint32_t*)(p0 + 8);
                pf[m][3] = *(const uint32_t*)(p0 + 8 * PSTRH + 8);
            }
            #pragma unroll
            for (int nb = 0; nb < 8; nb++) {
                const uint32_t* vw = sVw + (ks * 8 + t) * VSTRW + dg * 64 + nb * 8 + g;
                uint32_t b0 = vw[0];
                uint32_t b1 = vw[4 * VSTRW];
                #pragma unroll
                for (int m = 0; m < 4; m++)
                    mma_f16(o[m][nb], pf[m], b0, b1);
            }
        }
        __syncthreads();
    }

    #pragma unroll
    for (int m = 0; m < 2; m++)
        #pragma unroll
        for (int r = 0; r < 2; r++) {
            rs[m][r] += __shfl_xor_sync(0xffffffff, rs[m][r], 1);
            rs[m][r] += __shfl_xor_sync(0xffffffff, rs[m][r], 2);
        }
    if (t == 0) {
        #pragma unroll
        for (int m = 0; m < 2; m++)
            #pragma unroll
            for (int r = 0; r < 2; r++)
                smL[kh * 128 + qg * 32 + m * 16 + r * 8 + g] = rs[m][r];
    }
    __syncthreads();

    #pragma unroll
    for (int m = 0; m < 4; m++) {
        int qrow = qh * 64 + m * 16 + g;
        float inv0 = 1.f / (smL[qrow] + smL[128 + qrow]);
        float inv8 = 1.f / (smL[qrow + 8] + smL[128 + qrow + 8]);
        __half* out0 = out + (size_t)(b * SEQ + q0 + qrow) * DE + dg * 64;
        __half* out8 = out0 + 8 * DE;
        #pragma unroll
        for (int nb = 0; nb < 8; nb++) {
            *(__half2*)(out0 + nb * 8 + 2 * t) =
                __floats2half2_rn(o[m][nb][0] * inv0, o[m][nb][1] * inv0);
            *(__half2*)(out8 + nb * 8 + 2 * t) =
                __floats2half2_rn(o[m][nb][2] * inv8, o[m][nb][3] * inv8);
        }
    }
}

// ---------------- BatchNorm pieces ----------------
__global__ void bn_zero_kernel() {
    int tidx = threadIdx.x;
    g_sum[tidx] = 0.f;
    g_sumsq[tidx] = 0.f;
}

__global__ void bn_stats_kernel(const float* __restrict__ h) {
    const int c = threadIdx.x;
    const int r0 = blockIdx.x * 128;
    float s = 0.f, s2 = 0.f;
    #pragma unroll 4
    for (int r = 0; r < 128; r++) {
        float x = h[(size_t)(r0 + r) * DE + c];
        s += x;
        s2 += x * x;
    }
    atomicAdd(&g_sum[c], s);
    atomicAdd(&g_sumsq[c], s2);
}

__global__ void bn_finalize_kernel(const float* __restrict__ h,
                                   const float* __restrict__ x,
                                   const float* __restrict__ gamma,
                                   const float* __restrict__ beta,
                                   float* __restrict__ y) {
    const int idx = blockIdx.x * 256 + threadIdx.x;
    const int c0 = (idx * 4) & 255;
    const float invM = 1.f / (float)MTOT;
    float4 hv = ((const float4*)h)[idx];
    float4 xv = ((const float4*)x)[idx];
    float r[4];
    float hvv[4] = {hv.x, hv.y, hv.z, hv.w};
    float xvv[4] = {xv.x, xv.y, xv.z, xv.w};
    #pragma unroll
    for (int u = 0; u < 4; u++) {
        int c = c0 + u;
        float mean = g_sum[c] * invM;
        float var = g_sumsq[c] * invM - mean * mean;
        float rsv = rsqrtf(var + 1e-5f);
        float val = (hvv[u] - mean) * rsv * gamma[c] + beta[c];
        r[u] = fmaxf(val, 0.f) + xvv[u];
    }
    float4 ov = {r[0], r[1], r[2], r[3]};
    ((float4*)y)[idx] = ov;
}

// ---------------- launch ----------------
extern "C" void kernel_launch(void* const* d_in, const int* in_sizes, int n_in,
                              void* d_out, int out_size) {
    const float* x     = (const float*)d_in[0];
    const float* Wq    = (const float*)d_in[1];
    const float* bq    = (const float*)d_in[2];
    const float* Wk    = (const float*)d_in[3];
    const float* bk    = (const float*)d_in[4];
    const float* Wv    = (const float*)d_in[5];
    const float* bv    = (const float*)d_in[6];
    const float* Wl    = (const float*)d_in[7];
    const float* bl    = (const float*)d_in[8];
    const float* gamma = (const float*)d_in[9];
    const float* beta  = (const float*)d_in[10];
    float* out = (float*)d_out;

    __half *pxh, *pqh, *pkh, *pvh, *pattnh, *pwqt, *pwkt, *pwvt, *pwlt;
    float *ph;
    cudaGetSymbolAddress((void**)&pxh, g_xh);
    cudaGetSymbolAddress((void**)&pqh, g_qh);
    cudaGetSymbolAddress((void**)&pkh, g_kh);
    cudaGetSymbolAddress((void**)&pvh, g_vh);
    cudaGetSymbolAddress((void**)&pattnh, g_attnh);
    cudaGetSymbolAddress((void**)&pwqt, g_wqt);
    cudaGetSymbolAddress((void**)&pwkt, g_wkt);
    cudaGetSymbolAddress((void**)&pwvt, g_wvt);
    cudaGetSymbolAddress((void**)&pwlt, g_wlt);
    cudaGetSymbolAddress((void**)&ph, g_h);

    cudaFuncSetAttribute(attn_mma_kernel, cudaFuncAttributeMaxDynamicSharedMemorySize,
                         ATTN_SMEM);
    cudaFuncSetAttribute(gemm_f16_kernel, cudaFuncAttributeMaxDynamicSharedMemorySize,
                         GEMMH_SMEM);

    // conversions
    conv_x_kernel<<<(MTOT * DE) / 4 / 256, 256>>>(x, pxh);
    conv_wt_kernel<<<(DA * DE + 255) / 256, 256>>>(Wq, pwqt, DA);
    conv_wt_kernel<<<(DA * DE + 255) / 256, 256>>>(Wk, pwkt, DA);
    conv_wt_kernel<<<(DE * DE + 255) / 256, 256>>>(Wv, pwvt, DE);
    conv_wt_kernel<<<(DE * DE + 255) / 256, 256>>>(Wl, pwlt, DE);

    // projections (fp16 mma)
    gemm_f16_kernel<<<dim3(MTOT / 128, 1), 256, GEMMH_SMEM>>>(pxh, pwqt, bq, pqh, DA, 1);
    gemm_f16_kernel<<<dim3(MTOT / 128, 1), 256, GEMMH_SMEM>>>(pxh, pwkt, bk, pkh, DA, 1);
    gemm_f16_kernel<<<dim3(MTOT / 128, 4), 256, GEMMH_SMEM>>>(pxh, pwvt, bv, pvh, DE, 2);

    // attention (fp16 m16n8k16, 256 threads, fp16 output)
    attn_mma_kernel<<<dim3(SEQ / 128, BATCH), 256, ATTN_SMEM>>>(pqh, pkh, pvh, pattnh);

    // h = attn @ Wl + bl (fp16 mma, fp32 out)
    gemm_f16_kernel<<<dim3(MTOT / 128, 4), 256, GEMMH_SMEM>>>(pattnh, pwlt, bl, ph, DE, 0);

    // batchnorm + relu + residual
    bn_zero_kernel<<<1, 256>>>();
    bn_stats_kernel<<<MTOT / 128, 256>>>(ph);
    bn_finalize_kernel<<<(MTOT * DE) / 4 / 256, 256>>>(ph, x, gamma, beta, out);
}